// round 5
// baseline (speedup 1.0000x reference)
#include <cuda_runtime.h>
#include <cuda_bf16.h>
#include <mma.h>
#include <cstdint>

using namespace nvcuda;

#define N_ROWS 4096
#define D_GRP  512
#define V_IN   16
#define U_MID  64
#define H_DIM  8192
#define GCHUNK 16

#define A_LD   64                   // bf16 elems per A row (48 used)
#define B_LD   64                   // bf16 elems per B row (48 used)
#define DT_LD  136                  // f32 col stride for Dt (128 rows + 8 pad)
#define A_BYTES (128 * A_LD * 2)    // 16384
#define B_BYTES (U_MID * B_LD * 2)  // 8192
#define DT_BYTES (U_MID * DT_LD * 4)// 34816
#define POOL_BYTES DT_BYTES         // Dt aliases A+B (24576 < 34816)

__device__ __forceinline__ float ex2f(float v) {
    float r; asm("ex2.approx.f32 %0, %1;" : "=f"(r) : "f"(v)); return r;
}
// branchless exact ELU: max(v, exp(min(v,0)) - 1)
__device__ __forceinline__ float eluf(float v) {
    float t = fminf(v, 0.0f);
    float e = ex2f(t * 1.4426950408889634f);
    return fmaxf(v, e - 1.0f);
}
__device__ __forceinline__ uint32_t bfpack(float a, float b) {
    __nv_bfloat162 t = __floats2bfloat162_rn(a, b);
    return *reinterpret_cast<uint32_t*>(&t);
}
__device__ __forceinline__ float bfround(float v) {
    return __bfloat162float(__float2bfloat16_rn(v));
}

// ---------------------------------------------------------------------------
// Main kernel: CTA = 128 rows x 16 groups. Per group d:
//   A[128 x 48 bf16] = [x_hi | x_lo | x_hi], B[64 x 48 bf16] = [w_hi | w_hi | w_lo]
//   D = A@B^T via wmma (fp32 accum)  ->  +b1, ELU, dot W2, +b2.
// Dt (D transposed, fp32) aliases A/B in a shared pool; 4 barriers per group.
// ---------------------------------------------------------------------------
__global__ void __launch_bounds__(128)
div_encoder_main(const float* __restrict__ x,
                 const float* __restrict__ W1,
                 const float* __restrict__ b1,
                 const float* __restrict__ W2,
                 const float* __restrict__ b2,
                 float* __restrict__ out)
{
    __shared__ __align__(128) char pool[POOL_BYTES];
    __shared__ float sb1[U_MID];
    __shared__ float sw2[U_MID];
    __shared__ float sout[GCHUNK][128];

    __nv_bfloat16* As = reinterpret_cast<__nv_bfloat16*>(pool);
    __nv_bfloat16* Bs = reinterpret_cast<__nv_bfloat16*>(pool + A_BYTES);
    float*         Dt = reinterpret_cast<float*>(pool);

    const int tid   = threadIdx.x;
    const int wid   = tid >> 5;
    const int gbase = blockIdx.y * GCHUNK;
    const int row   = blockIdx.x * 128 + tid;

    const int bu = tid >> 1;   // B row (u) this thread covers
    const int bh = tid & 1;    // which 8-value half

    // ---- prefetch registers ----
    float4 xr0, xr1, xr2, xr3;   // x slice (16 floats, this thread's row)
    float4 wv0, wv1;             // W1 half-row (8 floats)
    float  bwv;                  // b1 (tid<64) or W2 (tid>=64)
    {
        const float* xp = x + (size_t)row * H_DIM + gbase * V_IN;
        xr0 = ((const float4*)xp)[0]; xr1 = ((const float4*)xp)[1];
        xr2 = ((const float4*)xp)[2]; xr3 = ((const float4*)xp)[3];
        const float* wp = W1 + (size_t)gbase * (U_MID * V_IN) + bu * V_IN + bh * 8;
        wv0 = ((const float4*)wp)[0]; wv1 = ((const float4*)wp)[1];
        bwv = (tid < 64) ? b1[gbase * U_MID + tid] : W2[gbase * U_MID + (tid - 64)];
    }

    for (int i = 0; i < GCHUNK; ++i) {
        // ---- build A row (hi | lo | hi) ----
        {
            float xs[16] = {xr0.x,xr0.y,xr0.z,xr0.w, xr1.x,xr1.y,xr1.z,xr1.w,
                            xr2.x,xr2.y,xr2.z,xr2.w, xr3.x,xr3.y,xr3.z,xr3.w};
            uint32_t hp[8], lp[8];
            #pragma unroll
            for (int j = 0; j < 8; ++j) {
                float a = xs[2*j], b = xs[2*j+1];
                float ah = bfround(a), bh2 = bfround(b);
                hp[j] = bfpack(ah, bh2);
                lp[j] = bfpack(a - ah, b - bh2);
            }
            uint4* Arow = reinterpret_cast<uint4*>(pool + tid * 128);
            uint4 h0 = make_uint4(hp[0],hp[1],hp[2],hp[3]);
            uint4 h1 = make_uint4(hp[4],hp[5],hp[6],hp[7]);
            uint4 l0 = make_uint4(lp[0],lp[1],lp[2],lp[3]);
            uint4 l1 = make_uint4(lp[4],lp[5],lp[6],lp[7]);
            Arow[0] = h0; Arow[1] = h1;     // cols  0-15: hi
            Arow[2] = l0; Arow[3] = l1;     // cols 16-31: lo
            Arow[4] = h0; Arow[5] = h1;     // cols 32-47: hi
        }
        // ---- build B half-row (hi | hi | lo) ----
        {
            float ws[8] = {wv0.x,wv0.y,wv0.z,wv0.w, wv1.x,wv1.y,wv1.z,wv1.w};
            uint32_t wh[4], wl[4];
            #pragma unroll
            for (int j = 0; j < 4; ++j) {
                float a = ws[2*j], b = ws[2*j+1];
                float ah = bfround(a), bh2 = bfround(b);
                wh[j] = bfpack(ah, bh2);
                wl[j] = bfpack(a - ah, b - bh2);
            }
            uint4* Brow = reinterpret_cast<uint4*>(pool + A_BYTES + bu * 128 + bh * 16);
            uint4 whi = make_uint4(wh[0],wh[1],wh[2],wh[3]);
            uint4 wlo = make_uint4(wl[0],wl[1],wl[2],wl[3]);
            Brow[0] = whi;   // cols  0-15: hi
            Brow[2] = whi;   // cols 16-31: hi
            Brow[4] = wlo;   // cols 32-47: lo
        }
        if (tid < 64) sb1[tid] = bwv; else sw2[tid - 64] = bwv;
        __syncthreads();   // (1) A/B/sb1/sw2 ready

        // ---- prefetch next group's x / W1 / bias while MMA runs ----
        if (i + 1 < GCHUNK) {
            const int gn = gbase + i + 1;
            const float* xp = x + (size_t)row * H_DIM + gn * V_IN;
            xr0 = ((const float4*)xp)[0]; xr1 = ((const float4*)xp)[1];
            xr2 = ((const float4*)xp)[2]; xr3 = ((const float4*)xp)[3];
            const float* wp = W1 + (size_t)gn * (U_MID * V_IN) + bu * V_IN + bh * 8;
            wv0 = ((const float4*)wp)[0]; wv1 = ((const float4*)wp)[1];
            bwv = (tid < 64) ? b1[gn * U_MID + tid] : W2[gn * U_MID + (tid - 64)];
        }

        // ---- wmma: D[128x64] = A[128x48] @ B[64x48]^T ----
        {
            wmma::fragment<wmma::matrix_a, 16, 16, 16, __nv_bfloat16, wmma::row_major> a0, a1;
            wmma::fragment<wmma::matrix_b, 16, 16, 16, __nv_bfloat16, wmma::col_major> bfr;
            wmma::fragment<wmma::accumulator, 16, 16, 16, float> cf[2][4];
            #pragma unroll
            for (int mi = 0; mi < 2; ++mi)
                #pragma unroll
                for (int n = 0; n < 4; ++n)
                    wmma::fill_fragment(cf[mi][n], 0.0f);

            #pragma unroll
            for (int k = 0; k < 3; ++k) {
                wmma::load_matrix_sync(a0, As + (wid * 2 + 0) * 16 * A_LD + k * 16, A_LD);
                wmma::load_matrix_sync(a1, As + (wid * 2 + 1) * 16 * A_LD + k * 16, A_LD);
                #pragma unroll
                for (int n = 0; n < 4; ++n) {
                    wmma::load_matrix_sync(bfr, Bs + n * 16 * B_LD + k * 16, B_LD);
                    wmma::mma_sync(cf[0][n], a0, bfr, cf[0][n]);
                    wmma::mma_sync(cf[1][n], a1, bfr, cf[1][n]);
                }
            }
            __syncthreads();   // (2) all MMA reads of A/B done (Dt aliases them)

            #pragma unroll
            for (int mi = 0; mi < 2; ++mi)
                #pragma unroll
                for (int n = 0; n < 4; ++n)
                    wmma::store_matrix_sync(Dt + n * 16 * DT_LD + (wid * 2 + mi) * 16,
                                            cf[mi][n], DT_LD, wmma::mem_col_major);
        }
        __syncthreads();   // (3) Dt visible to all

        // ---- epilogue: +b1, ELU, dot W2 (conflict-free column reads) ----
        {
            float acc0 = 0.f, acc1 = 0.f, acc2 = 0.f, acc3 = 0.f;
            #pragma unroll
            for (int u = 0; u < U_MID; u += 4) {
                float v0 = Dt[(u + 0) * DT_LD + tid] + sb1[u + 0];
                float v1 = Dt[(u + 1) * DT_LD + tid] + sb1[u + 1];
                float v2 = Dt[(u + 2) * DT_LD + tid] + sb1[u + 2];
                float v3 = Dt[(u + 3) * DT_LD + tid] + sb1[u + 3];
                acc0 = fmaf(eluf(v0), sw2[u + 0], acc0);
                acc1 = fmaf(eluf(v1), sw2[u + 1], acc1);
                acc2 = fmaf(eluf(v2), sw2[u + 2], acc2);
                acc3 = fmaf(eluf(v3), sw2[u + 3], acc3);
            }
            sout[i][tid] = (acc0 + acc1) + (acc2 + acc3);
        }
        __syncthreads();   // (4) Dt reads done before next iter overwrites pool
    }

    // ---- coalesced-ish output: 16 contiguous floats for this thread's row ----
    {
        float4* op = reinterpret_cast<float4*>(out + (size_t)row * D_GRP + gbase);
        const float4* bp = reinterpret_cast<const float4*>(b2 + gbase);
        #pragma unroll
        for (int j = 0; j < 4; ++j) {
            float4 b = bp[j];
            op[j] = make_float4(sout[4*j + 0][tid] + b.x,
                                sout[4*j + 1][tid] + b.y,
                                sout[4*j + 2][tid] + b.z,
                                sout[4*j + 3][tid] + b.w);
        }
    }
}

// ---------------------------------------------------------------------------
// Row L2 normalize, one warp per row.
// ---------------------------------------------------------------------------
__global__ void __launch_bounds__(256)
div_encoder_norm(float* __restrict__ y)
{
    const int row  = blockIdx.x * 8 + (threadIdx.x >> 5);
    const int lane = threadIdx.x & 31;
    float4* rp = reinterpret_cast<float4*>(y + (size_t)row * D_GRP);

    float4 v0 = rp[lane];
    float4 v1 = rp[lane + 32];
    float4 v2 = rp[lane + 64];
    float4 v3 = rp[lane + 96];

    float s = v0.x*v0.x + v0.y*v0.y + v0.z*v0.z + v0.w*v0.w
            + v1.x*v1.x + v1.y*v1.y + v1.z*v1.z + v1.w*v1.w
            + v2.x*v2.x + v2.y*v2.y + v2.z*v2.z + v2.w*v2.w
            + v3.x*v3.x + v3.y*v3.y + v3.z*v3.z + v3.w*v3.w;

    #pragma unroll
    for (int off = 16; off > 0; off >>= 1)
        s += __shfl_xor_sync(0xFFFFFFFFu, s, off);

    const float scale = 1.0f / fmaxf(sqrtf(s), 1e-12f);
    v0.x *= scale; v0.y *= scale; v0.z *= scale; v0.w *= scale;
    v1.x *= scale; v1.y *= scale; v1.z *= scale; v1.w *= scale;
    v2.x *= scale; v2.y *= scale; v2.z *= scale; v2.w *= scale;
    v3.x *= scale; v3.y *= scale; v3.z *= scale; v3.w *= scale;
    rp[lane]      = v0;
    rp[lane + 32] = v1;
    rp[lane + 64] = v2;
    rp[lane + 96] = v3;
}

extern "C" void kernel_launch(void* const* d_in, const int* in_sizes, int n_in,
                              void* d_out, int out_size)
{
    const float* x  = (const float*)d_in[0];
    const float* W1 = (const float*)d_in[1];
    const float* b1 = (const float*)d_in[2];
    const float* W2 = (const float*)d_in[3];
    const float* b2 = (const float*)d_in[4];
    float* out = (float*)d_out;

    dim3 grid1(N_ROWS / 128, D_GRP / GCHUNK);   // 32 x 32
    div_encoder_main<<<grid1, 128>>>(x, W1, b1, W2, b2, out);
    div_encoder_norm<<<N_ROWS / 8, 256>>>(out);
}

// round 6
// speedup vs baseline: 3.9498x; 3.9498x over previous
#include <cuda_runtime.h>
#include <cuda_bf16.h>
#include <cstdint>

#define N_ROWS 4096
#define D_GRP  512
#define V_IN   16
#define U_MID  64
#define H_DIM  8192
#define GCHUNK 8          // groups per CTA
#define NWARP  8          // warps per CTA (each owns 16 rows)

__device__ __forceinline__ float ex2f(float v) {
    float r; asm("ex2.approx.f32 %0, %1;" : "=f"(r) : "f"(v)); return r;
}
// branchless exact ELU: max(v, exp(min(v,0)) - 1)
__device__ __forceinline__ float eluf(float v) {
    float t = fminf(v, 0.0f);
    float e = ex2f(t * 1.4426950408889634f);
    return fmaxf(v, e - 1.0f);
}

// pack two fp32 -> bf16x2 (lo = a, hi = b), plus hi/lo split of a float pair
__device__ __forceinline__ uint32_t packbf2(float a, float b) {
    __nv_bfloat162 t = __floats2bfloat162_rn(a, b);
    return *reinterpret_cast<uint32_t*>(&t);
}
// split pair (a,b) into hi bf16x2 and lo bf16x2 (lo = exact residual)
__device__ __forceinline__ void split2(float a, float b, uint32_t& hi, uint32_t& lo) {
    hi = packbf2(a, b);
    float ah = __uint_as_float(hi << 16);
    float bh = __uint_as_float(hi & 0xFFFF0000u);
    lo = packbf2(a - ah, b - bh);
}

// mma.m16n8k16 row.col bf16 -> fp32 accumulate in place
__device__ __forceinline__ void mma16816(float* c, const uint32_t* a, uint32_t b0, uint32_t b1) {
    asm volatile(
        "mma.sync.aligned.m16n8k16.row.col.f32.bf16.bf16.f32 "
        "{%0,%1,%2,%3}, {%4,%5,%6,%7}, {%8,%9}, {%0,%1,%2,%3};"
        : "+f"(c[0]), "+f"(c[1]), "+f"(c[2]), "+f"(c[3])
        : "r"(a[0]), "r"(a[1]), "r"(a[2]), "r"(a[3]), "r"(b0), "r"(b1));
}

// ---------------------------------------------------------------------------
// Main kernel: CTA = 128 rows x 8 groups, 256 threads = 8 warps.
// Warp w owns rows [w*16, w*16+16); loops over the CTA's 8 groups with NO
// barriers. Per (warp, group): D[16x64] = A[16x48] @ B[64x48]^T via 24
// mma.m16n8k16, hi/lo split in K: A=[x_hi|x_lo|x_hi], B=[w_hi|w_hi|w_lo].
// b1 folded into accumulator init; ELU + dot(W2) on registers; quad-shfl
// reduce -> y. D never touches smem.
// ---------------------------------------------------------------------------
__global__ void __launch_bounds__(256)
div_encoder_main(const float* __restrict__ x,
                 const float* __restrict__ W1,
                 const float* __restrict__ b1,
                 const float* __restrict__ W2,
                 const float* __restrict__ b2,
                 float* __restrict__ out)
{
    __shared__ uint4 Bsm[GCHUNK][8][32];   // [g][nt][lane] = {bh0,bh1,bl0,bl1} 32KB
    __shared__ float b1s[GCHUNK * U_MID];  // 2KB
    __shared__ float w2s[GCHUNK * U_MID];  // 2KB
    __shared__ float sout[GCHUNK][128];    // 4KB

    const int tid   = threadIdx.x;
    const int wid   = tid >> 5;
    const int lane  = tid & 31;
    const int gbase = blockIdx.y * GCHUNK;
    const int rbase = blockIdx.x * 128;

    const int qr = lane >> 2;        // quad row id (0..7)
    const int qc = (lane & 3) * 2;   // quad col base (0,2,4,6)

    // ---- setup: warp w pre-converts W1 group (gbase+w) into fragment layout ----
    {
        const float* wg = W1 + (size_t)(gbase + wid) * (U_MID * V_IN);
        #pragma unroll
        for (int nt = 0; nt < 8; ++nt) {
            const int u = nt * 8 + qr;
            const float* wp = wg + u * V_IN;
            float2 p0 = *reinterpret_cast<const float2*>(wp + qc);
            float2 p1 = *reinterpret_cast<const float2*>(wp + qc + 8);
            uint32_t bh0, bl0, bh1, bl1;
            split2(p0.x, p0.y, bh0, bl0);
            split2(p1.x, p1.y, bh1, bl1);
            Bsm[wid][nt][lane] = make_uint4(bh0, bh1, bl0, bl1);
        }
        // flat copies of b1 / W2 for this CTA's 8 groups (contiguous in gmem)
        b1s[tid]       = b1[gbase * U_MID + tid];
        b1s[tid + 256] = b1[gbase * U_MID + tid + 256];
        w2s[tid]       = W2[gbase * U_MID + tid];
        w2s[tid + 256] = W2[gbase * U_MID + tid + 256];
    }
    __syncthreads();

    // ---- main loop: no barriers ----
    const int row0 = rbase + wid * 16 + qr;   // this thread's upper row
    const float* xrow0 = x + (size_t)row0 * H_DIM + gbase * V_IN + qc;
    const float* xrow1 = xrow0 + (size_t)8 * H_DIM;

    for (int g = 0; g < GCHUNK; ++g) {
        // A fragments from gmem (quad-coalesced float2 loads)
        uint32_t a_hi[4], a_lo[4];
        {
            const float* p = xrow0 + g * V_IN;
            const float* q = xrow1 + g * V_IN;
            float2 p00 = *reinterpret_cast<const float2*>(p);       // r0, k0-7
            float2 p01 = *reinterpret_cast<const float2*>(p + 8);   // r0, k8-15
            float2 p10 = *reinterpret_cast<const float2*>(q);       // r0+8, k0-7
            float2 p11 = *reinterpret_cast<const float2*>(q + 8);   // r0+8, k8-15
            split2(p00.x, p00.y, a_hi[0], a_lo[0]);
            split2(p10.x, p10.y, a_hi[1], a_lo[1]);
            split2(p01.x, p01.y, a_hi[2], a_lo[2]);
            split2(p11.x, p11.y, a_hi[3], a_lo[3]);
        }

        // accumulators initialized with b1 (column-constant)
        float c[8][4];
        #pragma unroll
        for (int nt = 0; nt < 8; ++nt) {
            float2 bb = *reinterpret_cast<const float2*>(&b1s[g * U_MID + nt * 8 + qc]);
            c[nt][0] = bb.x; c[nt][1] = bb.y; c[nt][2] = bb.x; c[nt][3] = bb.y;
        }

        #pragma unroll
        for (int nt = 0; nt < 8; ++nt) {
            uint4 B = Bsm[g][nt][lane];
            mma16816(c[nt], a_hi, B.x, B.y);   // hi*hi
            mma16816(c[nt], a_lo, B.x, B.y);   // lo*hi
            mma16816(c[nt], a_hi, B.z, B.w);   // hi*lo
        }

        // epilogue on registers: ELU + dot W2
        float y0 = 0.0f, y1 = 0.0f;
        #pragma unroll
        for (int nt = 0; nt < 8; ++nt) {
            float2 wv = *reinterpret_cast<const float2*>(&w2s[g * U_MID + nt * 8 + qc]);
            y0 = fmaf(eluf(c[nt][0]), wv.x, y0);
            y0 = fmaf(eluf(c[nt][1]), wv.y, y0);
            y1 = fmaf(eluf(c[nt][2]), wv.x, y1);
            y1 = fmaf(eluf(c[nt][3]), wv.y, y1);
        }
        // reduce across the quad (cols are split over lane&3)
        y0 += __shfl_xor_sync(0xFFFFFFFFu, y0, 1);
        y0 += __shfl_xor_sync(0xFFFFFFFFu, y0, 2);
        y1 += __shfl_xor_sync(0xFFFFFFFFu, y1, 1);
        y1 += __shfl_xor_sync(0xFFFFFFFFu, y1, 2);
        if ((lane & 3) == 0) {
            sout[g][wid * 16 + qr]     = y0;
            sout[g][wid * 16 + qr + 8] = y1;
        }
    }
    __syncthreads();

    // ---- coalesced output: 8 contiguous floats per row ----
    if (tid < 128) {
        const int row = rbase + tid;
        const float4* bp = reinterpret_cast<const float4*>(b2 + gbase);
        float4 b0 = bp[0], b1v = bp[1];
        float4 v0 = make_float4(sout[0][tid] + b0.x, sout[1][tid] + b0.y,
                                sout[2][tid] + b0.z, sout[3][tid] + b0.w);
        float4 v1 = make_float4(sout[4][tid] + b1v.x, sout[5][tid] + b1v.y,
                                sout[6][tid] + b1v.z, sout[7][tid] + b1v.w);
        float4* op = reinterpret_cast<float4*>(out + (size_t)row * D_GRP + gbase);
        op[0] = v0;
        op[1] = v1;
    }
}

// ---------------------------------------------------------------------------
// Row L2 normalize, one warp per row.
// ---------------------------------------------------------------------------
__global__ void __launch_bounds__(256)
div_encoder_norm(float* __restrict__ y)
{
    const int row  = blockIdx.x * 8 + (threadIdx.x >> 5);
    const int lane = threadIdx.x & 31;
    float4* rp = reinterpret_cast<float4*>(y + (size_t)row * D_GRP);

    float4 v0 = rp[lane];
    float4 v1 = rp[lane + 32];
    float4 v2 = rp[lane + 64];
    float4 v3 = rp[lane + 96];

    float s = v0.x*v0.x + v0.y*v0.y + v0.z*v0.z + v0.w*v0.w
            + v1.x*v1.x + v1.y*v1.y + v1.z*v1.z + v1.w*v1.w
            + v2.x*v2.x + v2.y*v2.y + v2.z*v2.z + v2.w*v2.w
            + v3.x*v3.x + v3.y*v3.y + v3.z*v3.z + v3.w*v3.w;

    #pragma unroll
    for (int off = 16; off > 0; off >>= 1)
        s += __shfl_xor_sync(0xFFFFFFFFu, s, off);

    const float scale = 1.0f / fmaxf(sqrtf(s), 1e-12f);
    v0.x *= scale; v0.y *= scale; v0.z *= scale; v0.w *= scale;
    v1.x *= scale; v1.y *= scale; v1.z *= scale; v1.w *= scale;
    v2.x *= scale; v2.y *= scale; v2.z *= scale; v2.w *= scale;
    v3.x *= scale; v3.y *= scale; v3.z *= scale; v3.w *= scale;
    rp[lane]      = v0;
    rp[lane + 32] = v1;
    rp[lane + 64] = v2;
    rp[lane + 96] = v3;
}

extern "C" void kernel_launch(void* const* d_in, const int* in_sizes, int n_in,
                              void* d_out, int out_size)
{
    const float* x  = (const float*)d_in[0];
    const float* W1 = (const float*)d_in[1];
    const float* b1 = (const float*)d_in[2];
    const float* W2 = (const float*)d_in[3];
    const float* b2 = (const float*)d_in[4];
    float* out = (float*)d_out;

    dim3 grid1(N_ROWS / 128, D_GRP / GCHUNK);   // 32 x 64
    div_encoder_main<<<grid1, 256>>>(x, W1, b1, W2, b2, out);
    div_encoder_norm<<<N_ROWS / 8, 256>>>(out);
}